// round 13
// baseline (speedup 1.0000x reference)
#include <cuda_runtime.h>
#include <cuda_bf16.h>
#include <math.h>
#include <stdint.h>

#define B 32
#define T 512
#define HID 512
#define VOCAB 4096
#define M_TOT (T * B)

// ---- recurrence tiling ----
#define NJT 16
#define NG  8
#define JW  32
#define GB  4
#define WS_STRIDE 516
#define SH_STRIDE 520

// ---- bulk-pipeline projection GEMM config ----
#define PM 256
#define PN 128
#define KC 64
#define NCHUNK (HID / KC)        // 8
#define BLK_ELEMS 8192           // 128x64 bf16 = 16KB block
#define PROJ_STAGE 98304u        // 96KB per stage
#define POFF_ALO 32768u
#define POFF_BHI 65536u
#define POFF_BLO 81920u
#define PROJ_SMEM (2 * 98304 + 32)

__device__ float         g_Hall[M_TOT * HID];
__device__ __nv_bfloat16 g_Ahi[M_TOT * HID];      // chunk-major swizzled blocks
__device__ __nv_bfloat16 g_Alo[M_TOT * HID];
__device__ __nv_bfloat16 g_Bhi[VOCAB * HID];
__device__ __nv_bfloat16 g_Blo[VOCAB * HID];
__device__ unsigned g_cnt[NG];
__device__ unsigned g_exit[NG];

// ============================================================================
// helpers
// ============================================================================
__device__ __forceinline__ uint32_t smem_u32(const void* p) {
    uint32_t a;
    asm("{ .reg .u64 t; cvta.to.shared.u64 t, %1; cvt.u32.u64 %0, t; }"
        : "=r"(a) : "l"(p));
    return a;
}

__device__ __forceinline__ void mbar_init(uint32_t a, uint32_t cnt) {
    asm volatile("mbarrier.init.shared.b64 [%0], %1;" :: "r"(a), "r"(cnt) : "memory");
}

__device__ __forceinline__ void mbar_expect_tx(uint32_t a, uint32_t bytes) {
    asm volatile("mbarrier.arrive.expect_tx.shared.b64 _, [%0], %1;"
                 :: "r"(a), "r"(bytes) : "memory");
}

__device__ __forceinline__ void mbar_wait(uint32_t addr, uint32_t parity) {
    asm volatile(
        "{\n\t.reg .pred P;\n"
        "WAITLP_%=:\n\t"
        "mbarrier.try_wait.parity.acquire.cta.shared::cta.b64 P, [%0], %1, 0x989680;\n\t"
        "@P bra.uni WAITDN_%=;\n\t"
        "bra.uni WAITLP_%=;\n"
        "WAITDN_%=:\n\t}"
        :: "r"(addr), "r"(parity) : "memory");
}

__device__ __forceinline__ void bulk_cp(uint32_t dst, const void* src,
                                        uint32_t bytes, uint32_t mbar) {
    asm volatile(
        "cp.async.bulk.shared::cluster.global.mbarrier::complete_tx::bytes "
        "[%0], [%1], %2, [%3];"
        :: "r"(dst), "l"(src), "r"(bytes), "r"(mbar) : "memory");
}

__device__ __forceinline__ void ldsm4(uint32_t* r, uint32_t addr) {
    asm volatile("ldmatrix.sync.aligned.m8n8.x4.shared.b16 {%0,%1,%2,%3}, [%4];"
                 : "=r"(r[0]), "=r"(r[1]), "=r"(r[2]), "=r"(r[3]) : "r"(addr));
}

__device__ __forceinline__ void mma_bf16(float* c, const uint32_t* a, const uint32_t* b) {
    asm volatile(
        "mma.sync.aligned.m16n8k16.row.col.f32.bf16.bf16.f32 "
        "{%0,%1,%2,%3}, {%4,%5,%6,%7}, {%8,%9}, {%0,%1,%2,%3};"
        : "+f"(c[0]), "+f"(c[1]), "+f"(c[2]), "+f"(c[3])
        : "r"(a[0]), "r"(a[1]), "r"(a[2]), "r"(a[3]), "r"(b[0]), "r"(b[1]));
}

__device__ __forceinline__ unsigned ld_acq(const unsigned* p) {
    unsigned v;
    asm volatile("ld.global.acquire.gpu.u32 %0, [%1];" : "=r"(v) : "l"(p));
    return v;
}

// swizzled element index inside a 128x64 block (units: bf16 elems)
__device__ __forceinline__ int swz_idx(int row, int col) {
    return (row << 6) + (((col >> 3) ^ (row & 7)) << 3) + (col & 7);
}

// ============================================================================
// Persistent recurrence (unchanged from R12)
// ============================================================================
__global__ void __launch_bounds__(256) rnn_persist(
    const int* __restrict__ X,
    const float* __restrict__ state,
    const float* __restrict__ W_xh,
    const float* __restrict__ W_hh,
    const float* __restrict__ b_h)
{
    extern __shared__ float smem[];
    float* Ws   = smem;
    float* sH   = Ws + JW * WS_STRIDE;
    float* sRed = sH + GB * SH_STRIDE;

    const int tid = threadIdx.x;
    const int jt  = blockIdx.x;
    const int grp = blockIdx.y;
    const int j0  = jt * JW;
    const int b0  = grp * GB;

    {
        const int lane8 = tid & 7;
        const int kk    = tid >> 3;
        for (int kb = 0; kb < HID; kb += 32) {
            const int k = kb + kk;
            float4 v = *reinterpret_cast<const float4*>(&W_hh[(size_t)k * HID + j0 + lane8 * 4]);
            Ws[(lane8 * 4 + 0) * WS_STRIDE + k] = v.x;
            Ws[(lane8 * 4 + 1) * WS_STRIDE + k] = v.y;
            Ws[(lane8 * 4 + 2) * WS_STRIDE + k] = v.z;
            Ws[(lane8 * 4 + 3) * WS_STRIDE + k] = v.w;
        }
    }

    const int jq = tid & 7;
    const int bb = (tid >> 3) & 3;
    const int ks = tid >> 5;
    const int kbase = ks * 64;

    int fb = -1, fj = -1;
    float bh_reg = 0.f;
    const int* xrow = 0;
    int fkc = 0, fcol = 0;
    if (tid < 128) {
        fb = b0 + (tid >> 5);
        fj = j0 + (tid & 31);
        bh_reg = __ldg(&b_h[fj]);
        xrow = X + fb * T;
        fkc  = fj >> 6;
        fcol = fj & 63;
    }

    __syncthreads();

    for (int t = 0; t < T; t++) {
        float eb = 0.f;
        if (tid < 128) {
            const int tok = __ldg(&xrow[t]);
            eb = __ldg(&W_xh[(size_t)tok * HID + fj]) + bh_reg;
        }

        const float* Hprev = (t == 0) ? state : (g_Hall + (size_t)(t - 1) * B * HID);
        for (int i = tid; i < GB * (HID / 4); i += 256) {
            const int bi  = i >> 7;
            const int kk4 = i & 127;
            float4 v = reinterpret_cast<const float4*>(&Hprev[(size_t)(b0 + bi) * HID])[kk4];
            *reinterpret_cast<float4*>(&sH[bi * SH_STRIDE + kk4 * 4]) = v;
        }
        __syncthreads();

        float acc0 = 0.f, acc1 = 0.f, acc2 = 0.f, acc3 = 0.f;
        const float* hrow = &sH[bb * SH_STRIDE + kbase];
        const float* w0 = &Ws[(jq +  0) * WS_STRIDE + kbase];
        const float* w1 = &Ws[(jq +  8) * WS_STRIDE + kbase];
        const float* w2 = &Ws[(jq + 16) * WS_STRIDE + kbase];
        const float* w3 = &Ws[(jq + 24) * WS_STRIDE + kbase];
        #pragma unroll
        for (int kk = 0; kk < 64; kk += 4) {
            const float4 h = *reinterpret_cast<const float4*>(&hrow[kk]);
            const float4 a = *reinterpret_cast<const float4*>(&w0[kk]);
            const float4 b = *reinterpret_cast<const float4*>(&w1[kk]);
            const float4 c = *reinterpret_cast<const float4*>(&w2[kk]);
            const float4 d = *reinterpret_cast<const float4*>(&w3[kk]);
            acc0 += a.x * h.x + a.y * h.y + a.z * h.z + a.w * h.w;
            acc1 += b.x * h.x + b.y * h.y + b.z * h.z + b.w * h.w;
            acc2 += c.x * h.x + c.y * h.y + c.z * h.z + c.w * h.w;
            acc3 += d.x * h.x + d.y * h.y + d.z * h.z + d.w * h.w;
        }
        sRed[ks * 128 + bb * 32 + jq +  0] = acc0;
        sRed[ks * 128 + bb * 32 + jq +  8] = acc1;
        sRed[ks * 128 + bb * 32 + jq + 16] = acc2;
        sRed[ks * 128 + bb * 32 + jq + 24] = acc3;
        __syncthreads();

        if (tid < 128) {
            float s = 0.f;
            #pragma unroll
            for (int q = 0; q < 8; q++) s += sRed[q * 128 + tid];
            s += eb;
            const float h = tanhf(s);
            const int m = t * B + fb;
            g_Hall[(size_t)m * HID + fj] = h;
            const __nv_bfloat16 hi = __float2bfloat16(h);
            const __nv_bfloat16 lo = __float2bfloat16(h - __bfloat162float(hi));
            const int idx = (((m >> 7) * NCHUNK + fkc) << 13)
                          + swz_idx(m & 127, fcol);
            g_Ahi[idx] = hi;
            g_Alo[idx] = lo;
        }
        __syncthreads();

        if (tid == 0) {
            asm volatile("red.release.gpu.global.add.u32 [%0], %1;"
                         :: "l"(&g_cnt[grp]), "r"(1u) : "memory");
            const unsigned target = (unsigned)(NJT * (t + 1));
            while (ld_acq(&g_cnt[grp]) < target) { }
        }
        __syncthreads();
    }

    if (tid == 0) {
        const unsigned v = atomicAdd(&g_exit[grp], 1u);
        if (v == NJT - 1) {
            g_cnt[grp]  = 0;
            g_exit[grp] = 0;
            __threadfence();
        }
    }
}

// ============================================================================
// Prep: transpose + split W_hq -> chunk-major swizzled Bhi/Blo (unchanged)
// ============================================================================
__global__ void __launch_bounds__(256) prep_b(const float* __restrict__ Wq)
{
    __shared__ float tl[32][33];
    const int n0 = blockIdx.x * 32;
    const int k0 = blockIdx.y * 32;
    const int tx = threadIdx.x;
    const int ty = threadIdx.y;

    #pragma unroll
    for (int i = 0; i < 32; i += 8)
        tl[ty + i][tx] = Wq[(size_t)(k0 + ty + i) * VOCAB + n0 + tx];
    __syncthreads();

    #pragma unroll
    for (int i = 0; i < 32; i += 8) {
        const float v = tl[tx][ty + i];
        const int n = n0 + ty + i;
        const int k = k0 + tx;
        const int idx = (((n >> 7) * NCHUNK + (k >> 6)) << 13)
                      + swz_idx(n & 127, k & 63);
        const __nv_bfloat16 hi = __float2bfloat16(v);
        g_Bhi[idx] = hi;
        g_Blo[idx] = __float2bfloat16(v - __bfloat162float(hi));
    }
}

// ============================================================================
// Bulk-pipelined projection GEMM with PASS-MAJOR mma ordering.
// Same-accumulator reuse distance = 8 MMAs (was 1) -> covers HMMA latency.
// ============================================================================
__device__ __forceinline__ void issue_chunk(uint32_t stage, uint32_t mbar,
                                            int c, int by, int bx)
{
    mbar_expect_tx(mbar, PROJ_STAGE);
    const size_t a0 = (size_t)((2 * by) * NCHUNK + c) * BLK_ELEMS;
    const size_t a1 = (size_t)((2 * by + 1) * NCHUNK + c) * BLK_ELEMS;
    const size_t b0 = (size_t)(bx * NCHUNK + c) * BLK_ELEMS;
    bulk_cp(stage,             g_Ahi + a0, 16384, mbar);
    bulk_cp(stage + 16384u,    g_Ahi + a1, 16384, mbar);
    bulk_cp(stage + POFF_ALO,          g_Alo + a0, 16384, mbar);
    bulk_cp(stage + POFF_ALO + 16384u, g_Alo + a1, 16384, mbar);
    bulk_cp(stage + POFF_BHI,  g_Bhi + b0, 16384, mbar);
    bulk_cp(stage + POFF_BLO,  g_Blo + b0, 16384, mbar);
}

__global__ void __launch_bounds__(512, 1) proj_bulk(
    const float* __restrict__ bq,
    float* __restrict__ C)
{
    extern __shared__ char smc[];
    const uint32_t sb  = smem_u32(smc);
    const uint32_t mb0 = sb + 2 * PROJ_STAGE;
    const uint32_t mb1 = mb0 + 8;

    const int tid  = threadIdx.x;
    const int lane = tid & 31;
    const int wid  = tid >> 5;
    const int wm   = wid & 3;
    const int wn   = wid >> 2;
    const int bx = blockIdx.x, by = blockIdx.y;
    const int bm = by * PM;
    const int bn = bx * PN;

    if (tid == 0) { mbar_init(mb0, 1); mbar_init(mb1, 1); }
    __syncthreads();

    if (tid == 0) {
        issue_chunk(sb,              mb0, 0, by, bx);
        issue_chunk(sb + PROJ_STAGE, mb1, 1, by, bx);
    }

    float acc[4][4][4];
    #pragma unroll
    for (int i = 0; i < 4; i++)
        #pragma unroll
        for (int j = 0; j < 4; j++)
            #pragma unroll
            for (int q = 0; q < 4; q++) acc[i][j][q] = 0.f;

    // per-lane fragment geometry (swizzle-aware)
    const int rA = wm * 64 + (lane & 15);
    const uint32_t cuA = (uint32_t)(lane >> 4);
    const uint32_t eA  = (uint32_t)(rA & 7);
    const int rB = wn * 32 + (lane & 7) + (((lane >> 4) & 1) << 3);
    const uint32_t cuB = (uint32_t)((lane >> 3) & 1);
    const uint32_t eB  = (uint32_t)(rB & 7);

    for (int c = 0; c < NCHUNK; c++) {
        mbar_wait((c & 1) ? mb1 : mb0, (uint32_t)((c >> 1) & 1));
        const uint32_t S = sb + (uint32_t)(c & 1) * PROJ_STAGE;

        #pragma unroll
        for (int ksi = 0; ksi < 4; ksi++) {
            // ---- B fragments for this k-slice
            uint32_t bh2[2][4], bl2[2][4];
            #pragma unroll
            for (int nf2 = 0; nf2 < 2; nf2++) {
                const uint32_t addr = S + POFF_BHI
                    + (uint32_t)(rB * 128 + nf2 * 2048)
                    + (((((uint32_t)ksi << 1) | cuB) ^ eB) << 4);
                ldsm4(bh2[nf2], addr);
                ldsm4(bl2[nf2], addr + (POFF_BLO - POFF_BHI));
            }
            // ---- process mf in pairs; pass-major over the pair's 8 accs
            #pragma unroll
            for (int mfp = 0; mfp < 2; mfp++) {
                uint32_t ah[2][4], al[2][4];
                #pragma unroll
                for (int m2 = 0; m2 < 2; m2++) {
                    const int mf = mfp * 2 + m2;
                    const uint32_t addr = S
                        + (uint32_t)(rA * 128 + mf * 2048)
                        + (((((uint32_t)ksi << 1) | cuA) ^ eA) << 4);
                    ldsm4(ah[m2], addr);
                    ldsm4(al[m2], addr + POFF_ALO);
                }
                // pass 0: hi*hi  — accs 0..7 in sequence (distance 8)
                #pragma unroll
                for (int m2 = 0; m2 < 2; m2++)
                    #pragma unroll
                    for (int nf = 0; nf < 4; nf++)
                        mma_bf16(acc[mfp * 2 + m2][nf], ah[m2],
                                 &bh2[nf >> 1][(nf & 1) * 2]);
                // pass 1: lo*hi
                #pragma unroll
                for (int m2 = 0; m2 < 2; m2++)
                    #pragma unroll
                    for (int nf = 0; nf < 4; nf++)
                        mma_bf16(acc[mfp * 2 + m2][nf], al[m2],
                                 &bh2[nf >> 1][(nf & 1) * 2]);
                // pass 2: hi*lo
                #pragma unroll
                for (int m2 = 0; m2 < 2; m2++)
                    #pragma unroll
                    for (int nf = 0; nf < 4; nf++)
                        mma_bf16(acc[mfp * 2 + m2][nf], ah[m2],
                                 &bl2[nf >> 1][(nf & 1) * 2]);
            }
        }
        __syncthreads();
        if (tid == 0 && c < NCHUNK - 2) {
            issue_chunk(S, (c & 1) ? mb1 : mb0, c + 2, by, bx);
        }
    }

    // epilogue: direct stores with bias
    #pragma unroll
    for (int mf = 0; mf < 4; mf++) {
        const int row0 = bm + wm * 64 + mf * 16 + (lane >> 2);
        #pragma unroll
        for (int nf = 0; nf < 4; nf++) {
            const int col = bn + wn * 32 + nf * 8 + ((lane & 3) << 1);
            const float2 bias = *reinterpret_cast<const float2*>(bq + col);
            float2 v0, v1;
            v0.x = acc[mf][nf][0] + bias.x;
            v0.y = acc[mf][nf][1] + bias.y;
            v1.x = acc[mf][nf][2] + bias.x;
            v1.y = acc[mf][nf][3] + bias.y;
            *reinterpret_cast<float2*>(&C[(size_t)row0 * VOCAB + col]) = v0;
            *reinterpret_cast<float2*>(&C[(size_t)(row0 + 8) * VOCAB + col]) = v1;
        }
    }
}

__global__ void copy_hfinal(float* __restrict__ out)
{
    int i = blockIdx.x * 256 + threadIdx.x;
    if (i < B * HID)
        out[i] = g_Hall[(size_t)(T - 1) * B * HID + i];
}

// ============================================================================
extern "C" void kernel_launch(void* const* d_in, const int* in_sizes, int n_in,
                              void* d_out, int out_size)
{
    const int*   X     = (const int*)d_in[0];
    const float* state = (const float*)d_in[1];
    const float* W_xh  = (const float*)d_in[2];
    const float* W_hh  = (const float*)d_in[3];
    const float* b_h   = (const float*)d_in[4];
    const float* W_hq  = (const float*)d_in[5];
    const float* b_q   = (const float*)d_in[6];
    float* out = (float*)d_out;

    prep_b<<<dim3(VOCAB / 32, HID / 32), dim3(32, 8)>>>(W_hq);

    const int rec_smem = (JW * WS_STRIDE + GB * SH_STRIDE + 8 * 128) * (int)sizeof(float);
    cudaFuncSetAttribute(rnn_persist, cudaFuncAttributeMaxDynamicSharedMemorySize, rec_smem);
    rnn_persist<<<dim3(NJT, NG), 256, rec_smem>>>(X, state, W_xh, W_hh, b_h);

    cudaFuncSetAttribute(proj_bulk, cudaFuncAttributeMaxDynamicSharedMemorySize, PROJ_SMEM);
    proj_bulk<<<dim3(VOCAB / PN, M_TOT / PM), 512, PROJ_SMEM>>>(b_q, out);

    if (out_size >= M_TOT * VOCAB + B * HID) {
        copy_hfinal<<<(B * HID + 255) / 256, 256>>>(out + (size_t)M_TOT * VOCAB);
    }
}

// round 15
// speedup vs baseline: 1.0538x; 1.0538x over previous
#include <cuda_runtime.h>
#include <cuda_bf16.h>
#include <cuda_fp16.h>
#include <math.h>
#include <stdint.h>

#define B 32
#define T 512
#define HID 512
#define VOCAB 4096
#define M_TOT (T * B)

// ---- recurrence tiling ----
#define NJT 16
#define NG  8
#define JW  32
#define GB  4
#define WS_STRIDE 516
#define SH_STRIDE 520

// ---- bulk-pipeline projection GEMM config (fp16 2-pass split) ----
#define PM 256
#define PN 128
#define KC 64
#define NCHUNK (HID / KC)        // 8
#define BLK_ELEMS 8192           // 128x64 fp16 = 16KB block
#define PROJ_STAGE 81920u        // 80KB per stage: Ahi 32K | Alo 32K | Bhi 16K
#define POFF_ALO 32768u
#define POFF_BHI 65536u
#define PROJ_SMEM (2 * 81920 + 32)

__device__ float  g_Hall[M_TOT * HID];
__device__ __half g_Ahi[M_TOT * HID];      // chunk-major swizzled blocks
__device__ __half g_Alo[M_TOT * HID];
__device__ __half g_Bhi[VOCAB * HID];      // chunk-major swizzled blocks
__device__ unsigned g_cnt[NG];
__device__ unsigned g_exit[NG];

// ============================================================================
// helpers
// ============================================================================
__device__ __forceinline__ uint32_t smem_u32(const void* p) {
    uint32_t a;
    asm("{ .reg .u64 t; cvta.to.shared.u64 t, %1; cvt.u32.u64 %0, t; }"
        : "=r"(a) : "l"(p));
    return a;
}

__device__ __forceinline__ void mbar_init(uint32_t a, uint32_t cnt) {
    asm volatile("mbarrier.init.shared.b64 [%0], %1;" :: "r"(a), "r"(cnt) : "memory");
}

__device__ __forceinline__ void mbar_expect_tx(uint32_t a, uint32_t bytes) {
    asm volatile("mbarrier.arrive.expect_tx.shared.b64 _, [%0], %1;"
                 :: "r"(a), "r"(bytes) : "memory");
}

__device__ __forceinline__ void mbar_wait(uint32_t addr, uint32_t parity) {
    asm volatile(
        "{\n\t.reg .pred P;\n"
        "WAITLP_%=:\n\t"
        "mbarrier.try_wait.parity.acquire.cta.shared::cta.b64 P, [%0], %1, 0x989680;\n\t"
        "@P bra.uni WAITDN_%=;\n\t"
        "bra.uni WAITLP_%=;\n"
        "WAITDN_%=:\n\t}"
        :: "r"(addr), "r"(parity) : "memory");
}

__device__ __forceinline__ void bulk_cp(uint32_t dst, const void* src,
                                        uint32_t bytes, uint32_t mbar) {
    asm volatile(
        "cp.async.bulk.shared::cluster.global.mbarrier::complete_tx::bytes "
        "[%0], [%1], %2, [%3];"
        :: "r"(dst), "l"(src), "r"(bytes), "r"(mbar) : "memory");
}

__device__ __forceinline__ void ldsm4(uint32_t* r, uint32_t addr) {
    asm volatile("ldmatrix.sync.aligned.m8n8.x4.shared.b16 {%0,%1,%2,%3}, [%4];"
                 : "=r"(r[0]), "=r"(r[1]), "=r"(r[2]), "=r"(r[3]) : "r"(addr));
}

__device__ __forceinline__ void mma_f16(float* c, const uint32_t* a, const uint32_t* b) {
    asm volatile(
        "mma.sync.aligned.m16n8k16.row.col.f32.f16.f16.f32 "
        "{%0,%1,%2,%3}, {%4,%5,%6,%7}, {%8,%9}, {%0,%1,%2,%3};"
        : "+f"(c[0]), "+f"(c[1]), "+f"(c[2]), "+f"(c[3])
        : "r"(a[0]), "r"(a[1]), "r"(a[2]), "r"(a[3]), "r"(b[0]), "r"(b[1]));
}

__device__ __forceinline__ unsigned ld_acq(const unsigned* p) {
    unsigned v;
    asm volatile("ld.global.acquire.gpu.u32 %0, [%1];" : "=r"(v) : "l"(p));
    return v;
}

// swizzled element index inside a 128x64 block (units: fp16 elems)
__device__ __forceinline__ int swz_idx(int row, int col) {
    return (row << 6) + (((col >> 3) ^ (row & 7)) << 3) + (col & 7);
}

// ============================================================================
// Persistent recurrence (structure unchanged; emits fp16 hi/lo of H)
// ============================================================================
__global__ void __launch_bounds__(256) rnn_persist(
    const int* __restrict__ X,
    const float* __restrict__ state,
    const float* __restrict__ W_xh,
    const float* __restrict__ W_hh,
    const float* __restrict__ b_h)
{
    extern __shared__ float smem[];
    float* Ws   = smem;
    float* sH   = Ws + JW * WS_STRIDE;
    float* sRed = sH + GB * SH_STRIDE;

    const int tid = threadIdx.x;
    const int jt  = blockIdx.x;
    const int grp = blockIdx.y;
    const int j0  = jt * JW;
    const int b0  = grp * GB;

    {
        const int lane8 = tid & 7;
        const int kk    = tid >> 3;
        for (int kb = 0; kb < HID; kb += 32) {
            const int k = kb + kk;
            float4 v = *reinterpret_cast<const float4*>(&W_hh[(size_t)k * HID + j0 + lane8 * 4]);
            Ws[(lane8 * 4 + 0) * WS_STRIDE + k] = v.x;
            Ws[(lane8 * 4 + 1) * WS_STRIDE + k] = v.y;
            Ws[(lane8 * 4 + 2) * WS_STRIDE + k] = v.z;
            Ws[(lane8 * 4 + 3) * WS_STRIDE + k] = v.w;
        }
    }

    const int jq = tid & 7;
    const int bb = (tid >> 3) & 3;
    const int ks = tid >> 5;
    const int kbase = ks * 64;

    int fb = -1, fj = -1;
    float bh_reg = 0.f;
    const int* xrow = 0;
    int fkc = 0, fcol = 0;
    if (tid < 128) {
        fb = b0 + (tid >> 5);
        fj = j0 + (tid & 31);
        bh_reg = __ldg(&b_h[fj]);
        xrow = X + fb * T;
        fkc  = fj >> 6;
        fcol = fj & 63;
    }

    __syncthreads();

    for (int t = 0; t < T; t++) {
        float eb = 0.f;
        if (tid < 128) {
            const int tok = __ldg(&xrow[t]);
            eb = __ldg(&W_xh[(size_t)tok * HID + fj]) + bh_reg;
        }

        const float* Hprev = (t == 0) ? state : (g_Hall + (size_t)(t - 1) * B * HID);
        for (int i = tid; i < GB * (HID / 4); i += 256) {
            const int bi  = i >> 7;
            const int kk4 = i & 127;
            float4 v = reinterpret_cast<const float4*>(&Hprev[(size_t)(b0 + bi) * HID])[kk4];
            *reinterpret_cast<float4*>(&sH[bi * SH_STRIDE + kk4 * 4]) = v;
        }
        __syncthreads();

        float acc0 = 0.f, acc1 = 0.f, acc2 = 0.f, acc3 = 0.f;
        const float* hrow = &sH[bb * SH_STRIDE + kbase];
        const float* w0 = &Ws[(jq +  0) * WS_STRIDE + kbase];
        const float* w1 = &Ws[(jq +  8) * WS_STRIDE + kbase];
        const float* w2 = &Ws[(jq + 16) * WS_STRIDE + kbase];
        const float* w3 = &Ws[(jq + 24) * WS_STRIDE + kbase];
        #pragma unroll
        for (int kk = 0; kk < 64; kk += 4) {
            const float4 h = *reinterpret_cast<const float4*>(&hrow[kk]);
            const float4 a = *reinterpret_cast<const float4*>(&w0[kk]);
            const float4 b = *reinterpret_cast<const float4*>(&w1[kk]);
            const float4 c = *reinterpret_cast<const float4*>(&w2[kk]);
            const float4 d = *reinterpret_cast<const float4*>(&w3[kk]);
            acc0 += a.x * h.x + a.y * h.y + a.z * h.z + a.w * h.w;
            acc1 += b.x * h.x + b.y * h.y + b.z * h.z + b.w * h.w;
            acc2 += c.x * h.x + c.y * h.y + c.z * h.z + c.w * h.w;
            acc3 += d.x * h.x + d.y * h.y + d.z * h.z + d.w * h.w;
        }
        sRed[ks * 128 + bb * 32 + jq +  0] = acc0;
        sRed[ks * 128 + bb * 32 + jq +  8] = acc1;
        sRed[ks * 128 + bb * 32 + jq + 16] = acc2;
        sRed[ks * 128 + bb * 32 + jq + 24] = acc3;
        __syncthreads();

        if (tid < 128) {
            float s = 0.f;
            #pragma unroll
            for (int q = 0; q < 8; q++) s += sRed[q * 128 + tid];
            s += eb;
            const float h = tanhf(s);
            const int m = t * B + fb;
            g_Hall[(size_t)m * HID + fj] = h;
            const __half hi = __float2half_rn(h);
            const __half lo = __float2half_rn(h - __half2float(hi));
            const int idx = (((m >> 7) * NCHUNK + fkc) << 13)
                          + swz_idx(m & 127, fcol);
            g_Ahi[idx] = hi;
            g_Alo[idx] = lo;
        }
        __syncthreads();

        if (tid == 0) {
            asm volatile("red.release.gpu.global.add.u32 [%0], %1;"
                         :: "l"(&g_cnt[grp]), "r"(1u) : "memory");
            const unsigned target = (unsigned)(NJT * (t + 1));
            while (ld_acq(&g_cnt[grp]) < target) { }
        }
        __syncthreads();
    }

    if (tid == 0) {
        const unsigned v = atomicAdd(&g_exit[grp], 1u);
        if (v == NJT - 1) {
            g_cnt[grp]  = 0;
            g_exit[grp] = 0;
            __threadfence();
        }
    }
}

// ============================================================================
// Prep: transpose W_hq (HID, VOCAB) -> chunk-major swizzled fp16 Bhi
// ============================================================================
__global__ void __launch_bounds__(256) prep_b(const float* __restrict__ Wq)
{
    __shared__ float tl[32][33];
    const int n0 = blockIdx.x * 32;
    const int k0 = blockIdx.y * 32;
    const int tx = threadIdx.x;
    const int ty = threadIdx.y;

    #pragma unroll
    for (int i = 0; i < 32; i += 8)
        tl[ty + i][tx] = Wq[(size_t)(k0 + ty + i) * VOCAB + n0 + tx];
    __syncthreads();

    #pragma unroll
    for (int i = 0; i < 32; i += 8) {
        const float v = tl[tx][ty + i];
        const int n = n0 + ty + i;
        const int k = k0 + tx;
        const int idx = (((n >> 7) * NCHUNK + (k >> 6)) << 13)
                      + swz_idx(n & 127, k & 63);
        g_Bhi[idx] = __float2half_rn(v);
    }
}

// ============================================================================
// Bulk-pipelined projection GEMM: fp16 2-pass split (hi*hi + lo*hi).
// CTA 256x128, 512 threads, K-chunk 64, 2-stage bulk pipeline.
// ============================================================================
__device__ __forceinline__ void issue_chunk(uint32_t stage, uint32_t mbar,
                                            int c, int by, int bx)
{
    mbar_expect_tx(mbar, PROJ_STAGE);
    const size_t a0 = (size_t)((2 * by) * NCHUNK + c) * BLK_ELEMS;
    const size_t a1 = (size_t)((2 * by + 1) * NCHUNK + c) * BLK_ELEMS;
    const size_t b0 = (size_t)(bx * NCHUNK + c) * BLK_ELEMS;
    bulk_cp(stage,                     g_Ahi + a0, 16384, mbar);
    bulk_cp(stage + 16384u,            g_Ahi + a1, 16384, mbar);
    bulk_cp(stage + POFF_ALO,          g_Alo + a0, 16384, mbar);
    bulk_cp(stage + POFF_ALO + 16384u, g_Alo + a1, 16384, mbar);
    bulk_cp(stage + POFF_BHI,          g_Bhi + b0, 16384, mbar);
}

__global__ void __launch_bounds__(512, 1) proj_bulk(
    const float* __restrict__ bq,
    float* __restrict__ C)
{
    extern __shared__ char smc[];
    const uint32_t sb  = smem_u32(smc);
    const uint32_t mb0 = sb + 2 * PROJ_STAGE;
    const uint32_t mb1 = mb0 + 8;

    const int tid  = threadIdx.x;
    const int lane = tid & 31;
    const int wid  = tid >> 5;
    const int wm   = wid & 3;
    const int wn   = wid >> 2;
    const int bx = blockIdx.x, by = blockIdx.y;
    const int bm = by * PM;
    const int bn = bx * PN;

    if (tid == 0) { mbar_init(mb0, 1); mbar_init(mb1, 1); }
    __syncthreads();

    if (tid == 0) {
        issue_chunk(sb,              mb0, 0, by, bx);
        issue_chunk(sb + PROJ_STAGE, mb1, 1, by, bx);
    }

    float acc[4][4][4];
    #pragma unroll
    for (int i = 0; i < 4; i++)
        #pragma unroll
        for (int j = 0; j < 4; j++)
            #pragma unroll
            for (int q = 0; q < 4; q++) acc[i][j][q] = 0.f;

    // per-lane fragment geometry (swizzle-aware)
    const int rA = wm * 64 + (lane & 15);
    const uint32_t cuA = (uint32_t)(lane >> 4);
    const uint32_t eA  = (uint32_t)(rA & 7);
    const int rB = wn * 32 + (lane & 7) + (((lane >> 4) & 1) << 3);
    const uint32_t cuB = (uint32_t)((lane >> 3) & 1);
    const uint32_t eB  = (uint32_t)(rB & 7);

    for (int c = 0; c < NCHUNK; c++) {
        mbar_wait((c & 1) ? mb1 : mb0, (uint32_t)((c >> 1) & 1));
        const uint32_t S = sb + (uint32_t)(c & 1) * PROJ_STAGE;

        #pragma unroll
        for (int ksi = 0; ksi < 4; ksi++) {
            // ---- B hi fragments for this k-slice
            uint32_t bh2[2][4];
            #pragma unroll
            for (int nf2 = 0; nf2 < 2; nf2++) {
                const uint32_t addr = S + POFF_BHI
                    + (uint32_t)(rB * 128 + nf2 * 2048)
                    + (((((uint32_t)ksi << 1) | cuB) ^ eB) << 4);
                ldsm4(bh2[nf2], addr);
            }
            // ---- mf pairs; pass-major over the pair's 8 accumulators
            #pragma unroll
            for (int mfp = 0; mfp < 2; mfp++) {
                uint32_t ah[2][4], al[2][4];
                #pragma unroll
                for (int m2 = 0; m2 < 2; m2++) {
                    const int mf = mfp * 2 + m2;
                    const uint32_t addr = S
                        + (uint32_t)(rA * 128 + mf * 2048)
                        + (((((uint32_t)ksi << 1) | cuA) ^ eA) << 4);
                    ldsm4(ah[m2], addr);
                    ldsm4(al[m2], addr + POFF_ALO);
                }
                // pass 0: hi*hi
                #pragma unroll
                for (int m2 = 0; m2 < 2; m2++)
                    #pragma unroll
                    for (int nf = 0; nf < 4; nf++)
                        mma_f16(acc[mfp * 2 + m2][nf], ah[m2],
                                &bh2[nf >> 1][(nf & 1) * 2]);
                // pass 1: lo*hi
                #pragma unroll
                for (int m2 = 0; m2 < 2; m2++)
                    #pragma unroll
                    for (int nf = 0; nf < 4; nf++)
                        mma_f16(acc[mfp * 2 + m2][nf], al[m2],
                                &bh2[nf >> 1][(nf & 1) * 2]);
            }
        }
        __syncthreads();
        if (tid == 0 && c < NCHUNK - 2) {
            issue_chunk(S, (c & 1) ? mb1 : mb0, c + 2, by, bx);
        }
    }

    // epilogue: direct stores with bias
    #pragma unroll
    for (int mf = 0; mf < 4; mf++) {
        const int row0 = bm + wm * 64 + mf * 16 + (lane >> 2);
        #pragma unroll
        for (int nf = 0; nf < 4; nf++) {
            const int col = bn + wn * 32 + nf * 8 + ((lane & 3) << 1);
            const float2 bias = *reinterpret_cast<const float2*>(bq + col);
            float2 v0, v1;
            v0.x = acc[mf][nf][0] + bias.x;
            v0.y = acc[mf][nf][1] + bias.y;
            v1.x = acc[mf][nf][2] + bias.x;
            v1.y = acc[mf][nf][3] + bias.y;
            *reinterpret_cast<float2*>(&C[(size_t)row0 * VOCAB + col]) = v0;
            *reinterpret_cast<float2*>(&C[(size_t)(row0 + 8) * VOCAB + col]) = v1;
        }
    }
}

__global__ void copy_hfinal(float* __restrict__ out)
{
    int i = blockIdx.x * 256 + threadIdx.x;
    if (i < B * HID)
        out[i] = g_Hall[(size_t)(T - 1) * B * HID + i];
}

// ============================================================================
extern "C" void kernel_launch(void* const* d_in, const int* in_sizes, int n_in,
                              void* d_out, int out_size)
{
    const int*   X     = (const int*)d_in[0];
    const float* state = (const float*)d_in[1];
    const float* W_xh  = (const float*)d_in[2];
    const float* W_hh  = (const float*)d_in[3];
    const float* b_h   = (const float*)d_in[4];
    const float* W_hq  = (const float*)d_in[5];
    const float* b_q   = (const float*)d_in[6];
    float* out = (float*)d_out;

    prep_b<<<dim3(VOCAB / 32, HID / 32), dim3(32, 8)>>>(W_hq);

    const int rec_smem = (JW * WS_STRIDE + GB * SH_STRIDE + 8 * 128) * (int)sizeof(float);
    cudaFuncSetAttribute(rnn_persist, cudaFuncAttributeMaxDynamicSharedMemorySize, rec_smem);
    rnn_persist<<<dim3(NJT, NG), 256, rec_smem>>>(X, state, W_xh, W_hh, b_h);

    cudaFuncSetAttribute(proj_bulk, cudaFuncAttributeMaxDynamicSharedMemorySize, PROJ_SMEM);
    proj_bulk<<<dim3(VOCAB / PN, M_TOT / PM), 512, PROJ_SMEM>>>(b_q, out);

    if (out_size >= M_TOT * VOCAB + B * HID) {
        copy_hfinal<<<(B * HID + 255) / 256, 256>>>(out + (size_t)M_TOT * VOCAB);
    }
}

// round 17
// speedup vs baseline: 1.2480x; 1.1843x over previous
#include <cuda_runtime.h>
#include <cuda_bf16.h>
#include <cuda_fp16.h>
#include <math.h>
#include <stdint.h>

#define B 32
#define T 512
#define HID 512
#define VOCAB 4096
#define M_TOT (T * B)

// ---- cluster recurrence config ----
#define CLS 16                   // CTAs per cluster (one batch group)
#define NG  8                    // batch groups
#define JW  32                   // j per CTA
#define GB  4                    // batches per group
#define WST_STRIDE 36            // padded floats per k-row of Wst (144B, 16B-mult)
#define WST_FLOATS (HID * WST_STRIDE)          // 18432
#define SH4_F      WST_FLOATS                  // float offset of H4 double buffer
#define STG_F      (SH4_F + 2 * HID * GB)      // float offset of staging (after 4096)
#define REC_SMEM   ((STG_F + 128) * 4)         // bytes

// ---- bulk-pipeline projection GEMM config (fp16 2-pass split) ----
#define PM 256
#define PN 128
#define KC 64
#define NCHUNK (HID / KC)        // 8
#define BLK_ELEMS 8192           // 128x64 fp16 = 16KB block
#define PROJ_STAGE 81920u        // Ahi 32K | Alo 32K | Bhi 16K
#define POFF_ALO 32768u
#define POFF_BHI 65536u
#define PROJ_SMEM (2 * 81920 + 32)

__device__ __half g_Ahi[M_TOT * HID];      // chunk-major swizzled blocks
__device__ __half g_Alo[M_TOT * HID];
__device__ __half g_Bhi[VOCAB * HID];
__device__ float  g_Hfin[B * HID];

// ============================================================================
// helpers
// ============================================================================
__device__ __forceinline__ uint32_t smem_u32(const void* p) {
    uint32_t a;
    asm("{ .reg .u64 t; cvta.to.shared.u64 t, %1; cvt.u32.u64 %0, t; }"
        : "=r"(a) : "l"(p));
    return a;
}

__device__ __forceinline__ void mbar_init(uint32_t a, uint32_t cnt) {
    asm volatile("mbarrier.init.shared.b64 [%0], %1;" :: "r"(a), "r"(cnt) : "memory");
}

__device__ __forceinline__ void mbar_expect_tx(uint32_t a, uint32_t bytes) {
    asm volatile("mbarrier.arrive.expect_tx.shared.b64 _, [%0], %1;"
                 :: "r"(a), "r"(bytes) : "memory");
}

__device__ __forceinline__ void mbar_wait(uint32_t addr, uint32_t parity) {
    asm volatile(
        "{\n\t.reg .pred P;\n"
        "WAITLP_%=:\n\t"
        "mbarrier.try_wait.parity.acquire.cta.shared::cta.b64 P, [%0], %1, 0x989680;\n\t"
        "@P bra.uni WAITDN_%=;\n\t"
        "bra.uni WAITLP_%=;\n"
        "WAITDN_%=:\n\t}"
        :: "r"(addr), "r"(parity) : "memory");
}

__device__ __forceinline__ void bulk_cp(uint32_t dst, const void* src,
                                        uint32_t bytes, uint32_t mbar) {
    asm volatile(
        "cp.async.bulk.shared::cluster.global.mbarrier::complete_tx::bytes "
        "[%0], [%1], %2, [%3];"
        :: "r"(dst), "l"(src), "r"(bytes), "r"(mbar) : "memory");
}

__device__ __forceinline__ void ldsm4(uint32_t* r, uint32_t addr) {
    asm volatile("ldmatrix.sync.aligned.m8n8.x4.shared.b16 {%0,%1,%2,%3}, [%4];"
                 : "=r"(r[0]), "=r"(r[1]), "=r"(r[2]), "=r"(r[3]) : "r"(addr));
}

__device__ __forceinline__ void mma_f16(float* c, const uint32_t* a, const uint32_t* b) {
    asm volatile(
        "mma.sync.aligned.m16n8k16.row.col.f32.f16.f16.f32 "
        "{%0,%1,%2,%3}, {%4,%5,%6,%7}, {%8,%9}, {%0,%1,%2,%3};"
        : "+f"(c[0]), "+f"(c[1]), "+f"(c[2]), "+f"(c[3])
        : "r"(a[0]), "r"(a[1]), "r"(a[2]), "r"(a[3]), "r"(b[0]), "r"(b[1]));
}

// swizzled element index inside a 128x64 block (units: fp16 elems)
__device__ __forceinline__ int swz_idx(int row, int col) {
    return (row << 6) + (((col >> 3) ^ (row & 7)) << 3) + (col & 7);
}

// ============================================================================
// Cluster recurrence: H lives in SMEM, exchanged via DSMEM each step.
// grid (16, 8); cluster = the 16 x-CTAs of one batch group.
// CTA(jt, grp): owns j in [jt*32, jt*32+32), batches [grp*4, grp*4+4).
// Per CTA smem: Wst[512][36] (W_hh^T slice), H4[2][512][4] (double buffer,
// float4-packed over batch), sStage[8][16].
// ============================================================================
__global__ void __launch_bounds__(256) __cluster_dims__(CLS, 1, 1)
rnn_cluster(
    const int* __restrict__ X,
    const float* __restrict__ state,
    const float* __restrict__ W_xh,
    const float* __restrict__ W_hh,
    const float* __restrict__ b_h)
{
    extern __shared__ float sm[];
    float* Wst    = sm;                 // [512][36]  Wst[k][jl] = W_hh[k][j0+jl]
    float* H4     = sm + SH4_F;         // [2][512][4]
    float* sStage = sm + STG_F;         // [8][16]

    const int tid  = threadIdx.x;
    const int lane = tid & 31;
    const int w    = tid >> 5;          // warp id = j-quad index
    const int jt   = blockIdx.x;        // cluster rank
    const int grp  = blockIdx.y;
    const int j0   = jt * JW;
    const int b0   = grp * GB;

    // ---- preload Wst (transposed W_hh slice), once
    for (int i = tid; i < HID * 8; i += 256) {
        const int k = i >> 3;
        const int q = i & 7;
        float4 v = *reinterpret_cast<const float4*>(&W_hh[(size_t)k * HID + j0 + q * 4]);
        float* d = &Wst[k * WST_STRIDE + q * 4];
        d[0] = v.x; d[1] = v.y; d[2] = v.z; d[3] = v.w;
    }
    // ---- initial H (buffer 0) from global state: H4[0][k][b] = state[b0+b][k]
    for (int i = tid; i < GB * HID; i += 256) {
        const int b = i >> 9;           // i / 512
        const int k = i & (HID - 1);
        H4[(size_t)k * 4 + b] = state[(size_t)(b0 + b) * HID + k];
    }
    __syncthreads();

    // ---- finalizer identity (tid < 128): output (w'=tid>>4, ji=(tid>>2)&3, bi=tid&3)
    int fjg = 0, fbg = 0, fkc = 0, fcol = 0;
    float bh_reg = 0.f;
    const int* xrow = 0;
    if (tid < 128) {
        fjg = j0 + ((tid >> 4) << 2) + ((tid >> 2) & 3);
        fbg = b0 + (tid & 3);
        bh_reg = __ldg(&b_h[fjg]);
        xrow = X + fbg * T;
        fkc  = fjg >> 6;
        fcol = fjg & 63;
    }

    int cur = 0;

    for (int t = 0; t < T; t++) {
        // prefetch embedding + bias (independent of H_t)
        float eb = 0.f;
        if (tid < 128) {
            const int tok = __ldg(&xrow[t]);
            eb = __ldg(&W_xh[(size_t)tok * HID + fjg]) + bh_reg;
        }

        // ---- compute: thread owns (j-quad w, all 4 b, k = kk*32 + lane)
        float acc[4][4];
        #pragma unroll
        for (int ji = 0; ji < 4; ji++)
            #pragma unroll
            for (int bi = 0; bi < 4; bi++) acc[ji][bi] = 0.f;

        const float4* Hc = reinterpret_cast<const float4*>(H4 + (size_t)cur * HID * 4);
        #pragma unroll 4
        for (int kk = 0; kk < 16; kk++) {
            const int k = kk * 32 + lane;
            const float4 wv = *reinterpret_cast<const float4*>(&Wst[k * WST_STRIDE + w * 4]);
            const float4 hv = Hc[k];
            acc[0][0] += wv.x * hv.x;  acc[0][1] += wv.x * hv.y;
            acc[0][2] += wv.x * hv.z;  acc[0][3] += wv.x * hv.w;
            acc[1][0] += wv.y * hv.x;  acc[1][1] += wv.y * hv.y;
            acc[1][2] += wv.y * hv.z;  acc[1][3] += wv.y * hv.w;
            acc[2][0] += wv.z * hv.x;  acc[2][1] += wv.z * hv.y;
            acc[2][2] += wv.z * hv.z;  acc[2][3] += wv.z * hv.w;
            acc[3][0] += wv.w * hv.x;  acc[3][1] += wv.w * hv.y;
            acc[3][2] += wv.w * hv.z;  acc[3][3] += wv.w * hv.w;
        }

        // ---- butterfly reduce across the 32 k-lanes
        #pragma unroll
        for (int s = 16; s >= 1; s >>= 1) {
            #pragma unroll
            for (int ji = 0; ji < 4; ji++)
                #pragma unroll
                for (int bi = 0; bi < 4; bi++)
                    acc[ji][bi] += __shfl_xor_sync(0xFFFFFFFFu, acc[ji][bi], s);
        }
        if (lane == 0) {
            #pragma unroll
            for (int ji = 0; ji < 4; ji++)
                #pragma unroll
                for (int bi = 0; bi < 4; bi++)
                    sStage[w * 16 + ji * 4 + bi] = acc[ji][bi];
        }
        __syncthreads();

        // ---- finalize + DSMEM scatter to all 16 cluster CTAs
        const int nxt = cur ^ 1;
        float h = 0.f;
        if (tid < 128) {
            float s = sStage[(tid >> 4) * 16 + (tid & 15)] + eb;
            h = tanhf(s);
            const uint32_t loff = smem_u32(sm)
                + (uint32_t)((SH4_F + nxt * HID * 4 + fjg * 4 + (tid & 3)) * 4);
            #pragma unroll
            for (int r = 0; r < CLS; r++) {
                uint32_t ra;
                asm volatile("mapa.shared::cluster.u32 %0, %1, %2;"
                             : "=r"(ra) : "r"(loff), "r"(r));
                asm volatile("st.shared::cluster.f32 [%0], %1;"
                             :: "r"(ra), "f"(h) : "memory");
            }
        }

        // arrive releases the DSMEM stores; hide global stores before wait
        asm volatile("barrier.cluster.arrive.aligned;" ::: "memory");
        if (tid < 128) {
            const int m = t * B + fbg;
            const __half hi = __float2half_rn(h);
            const __half lo = __float2half_rn(h - __half2float(hi));
            const int idx = (((m >> 7) * NCHUNK + fkc) << 13)
                          + swz_idx(m & 127, fcol);
            g_Ahi[idx] = hi;
            g_Alo[idx] = lo;
            if (t == T - 1) g_Hfin[(size_t)fbg * HID + fjg] = h;
        }
        asm volatile("barrier.cluster.wait.aligned;" ::: "memory");

        cur = nxt;
    }
}

// ============================================================================
// Prep: transpose W_hq (HID, VOCAB) -> chunk-major swizzled fp16 Bhi
// ============================================================================
__global__ void __launch_bounds__(256) prep_b(const float* __restrict__ Wq)
{
    __shared__ float tl[32][33];
    const int n0 = blockIdx.x * 32;
    const int k0 = blockIdx.y * 32;
    const int tx = threadIdx.x;
    const int ty = threadIdx.y;

    #pragma unroll
    for (int i = 0; i < 32; i += 8)
        tl[ty + i][tx] = Wq[(size_t)(k0 + ty + i) * VOCAB + n0 + tx];
    __syncthreads();

    #pragma unroll
    for (int i = 0; i < 32; i += 8) {
        const float v = tl[tx][ty + i];
        const int n = n0 + ty + i;
        const int k = k0 + tx;
        const int idx = (((n >> 7) * NCHUNK + (k >> 6)) << 13)
                      + swz_idx(n & 127, k & 63);
        g_Bhi[idx] = __float2half_rn(v);
    }
}

// ============================================================================
// Bulk-pipelined projection GEMM: fp16 2-pass split (unchanged from R15)
// ============================================================================
__device__ __forceinline__ void issue_chunk(uint32_t stage, uint32_t mbar,
                                            int c, int by, int bx)
{
    mbar_expect_tx(mbar, PROJ_STAGE);
    const size_t a0 = (size_t)((2 * by) * NCHUNK + c) * BLK_ELEMS;
    const size_t a1 = (size_t)((2 * by + 1) * NCHUNK + c) * BLK_ELEMS;
    const size_t b0 = (size_t)(bx * NCHUNK + c) * BLK_ELEMS;
    bulk_cp(stage,                     g_Ahi + a0, 16384, mbar);
    bulk_cp(stage + 16384u,            g_Ahi + a1, 16384, mbar);
    bulk_cp(stage + POFF_ALO,          g_Alo + a0, 16384, mbar);
    bulk_cp(stage + POFF_ALO + 16384u, g_Alo + a1, 16384, mbar);
    bulk_cp(stage + POFF_BHI,          g_Bhi + b0, 16384, mbar);
}

__global__ void __launch_bounds__(512, 1) proj_bulk(
    const float* __restrict__ bq,
    float* __restrict__ C)
{
    extern __shared__ char smc[];
    const uint32_t sb  = smem_u32(smc);
    const uint32_t mb0 = sb + 2 * PROJ_STAGE;
    const uint32_t mb1 = mb0 + 8;

    const int tid  = threadIdx.x;
    const int lane = tid & 31;
    const int wid  = tid >> 5;
    const int wm   = wid & 3;
    const int wn   = wid >> 2;
    const int bx = blockIdx.x, by = blockIdx.y;
    const int bm = by * PM;
    const int bn = bx * PN;

    if (tid == 0) { mbar_init(mb0, 1); mbar_init(mb1, 1); }
    __syncthreads();

    if (tid == 0) {
        issue_chunk(sb,              mb0, 0, by, bx);
        issue_chunk(sb + PROJ_STAGE, mb1, 1, by, bx);
    }

    float acc[4][4][4];
    #pragma unroll
    for (int i = 0; i < 4; i++)
        #pragma unroll
        for (int j = 0; j < 4; j++)
            #pragma unroll
            for (int q = 0; q < 4; q++) acc[i][j][q] = 0.f;

    const int rA = wm * 64 + (lane & 15);
    const uint32_t cuA = (uint32_t)(lane >> 4);
    const uint32_t eA  = (uint32_t)(rA & 7);
    const int rB = wn * 32 + (lane & 7) + (((lane >> 4) & 1) << 3);
    const uint32_t cuB = (uint32_t)((lane >> 3) & 1);
    const uint32_t eB  = (uint32_t)(rB & 7);

    for (int c = 0; c < NCHUNK; c++) {
        mbar_wait((c & 1) ? mb1 : mb0, (uint32_t)((c >> 1) & 1));
        const uint32_t S = sb + (uint32_t)(c & 1) * PROJ_STAGE;

        #pragma unroll
        for (int ksi = 0; ksi < 4; ksi++) {
            uint32_t bh2[2][4];
            #pragma unroll
            for (int nf2 = 0; nf2 < 2; nf2++) {
                const uint32_t addr = S + POFF_BHI
                    + (uint32_t)(rB * 128 + nf2 * 2048)
                    + (((((uint32_t)ksi << 1) | cuB) ^ eB) << 4);
                ldsm4(bh2[nf2], addr);
            }
            #pragma unroll
            for (int mfp = 0; mfp < 2; mfp++) {
                uint32_t ah[2][4], al[2][4];
                #pragma unroll
                for (int m2 = 0; m2 < 2; m2++) {
                    const int mf = mfp * 2 + m2;
                    const uint32_t addr = S
                        + (uint32_t)(rA * 128 + mf * 2048)
                        + (((((uint32_t)ksi << 1) | cuA) ^ eA) << 4);
                    ldsm4(ah[m2], addr);
                    ldsm4(al[m2], addr + POFF_ALO);
                }
                #pragma unroll
                for (int m2 = 0; m2 < 2; m2++)
                    #pragma unroll
                    for (int nf = 0; nf < 4; nf++)
                        mma_f16(acc[mfp * 2 + m2][nf], ah[m2],
                                &bh2[nf >> 1][(nf & 1) * 2]);
                #pragma unroll
                for (int m2 = 0; m2 < 2; m2++)
                    #pragma unroll
                    for (int nf = 0; nf < 4; nf++)
                        mma_f16(acc[mfp * 2 + m2][nf], al[m2],
                                &bh2[nf >> 1][(nf & 1) * 2]);
            }
        }
        __syncthreads();
        if (tid == 0 && c < NCHUNK - 2) {
            issue_chunk(S, (c & 1) ? mb1 : mb0, c + 2, by, bx);
        }
    }

    #pragma unroll
    for (int mf = 0; mf < 4; mf++) {
        const int row0 = bm + wm * 64 + mf * 16 + (lane >> 2);
        #pragma unroll
        for (int nf = 0; nf < 4; nf++) {
            const int col = bn + wn * 32 + nf * 8 + ((lane & 3) << 1);
            const float2 bias = *reinterpret_cast<const float2*>(bq + col);
            float2 v0, v1;
            v0.x = acc[mf][nf][0] + bias.x;
            v0.y = acc[mf][nf][1] + bias.y;
            v1.x = acc[mf][nf][2] + bias.x;
            v1.y = acc[mf][nf][3] + bias.y;
            *reinterpret_cast<float2*>(&C[(size_t)row0 * VOCAB + col]) = v0;
            *reinterpret_cast<float2*>(&C[(size_t)(row0 + 8) * VOCAB + col]) = v1;
        }
    }
}

__global__ void copy_hfinal(float* __restrict__ out)
{
    int i = blockIdx.x * 256 + threadIdx.x;
    if (i < B * HID)
        out[i] = g_Hfin[i];
}

// ============================================================================
extern "C" void kernel_launch(void* const* d_in, const int* in_sizes, int n_in,
                              void* d_out, int out_size)
{
    const int*   X     = (const int*)d_in[0];
    const float* state = (const float*)d_in[1];
    const float* W_xh  = (const float*)d_in[2];
    const float* W_hh  = (const float*)d_in[3];
    const float* b_h   = (const float*)d_in[4];
    const float* W_hq  = (const float*)d_in[5];
    const float* b_q   = (const float*)d_in[6];
    float* out = (float*)d_out;

    prep_b<<<dim3(VOCAB / 32, HID / 32), dim3(32, 8)>>>(W_hq);

    cudaFuncSetAttribute(rnn_cluster, cudaFuncAttributeMaxDynamicSharedMemorySize, REC_SMEM);
    cudaFuncSetAttribute(rnn_cluster, cudaFuncAttributeNonPortableClusterSizeAllowed, 1);
    rnn_cluster<<<dim3(CLS, NG), 256, REC_SMEM>>>(X, state, W_xh, W_hh, b_h);

    cudaFuncSetAttribute(proj_bulk, cudaFuncAttributeMaxDynamicSharedMemorySize, PROJ_SMEM);
    proj_bulk<<<dim3(VOCAB / PN, M_TOT / PM), 512, PROJ_SMEM>>>(b_q, out);

    if (out_size >= M_TOT * VOCAB + B * HID) {
        copy_hfinal<<<(B * HID + 255) / 256, 256>>>(out + (size_t)M_TOT * VOCAB);
    }
}